// round 8
// baseline (speedup 1.0000x reference)
#include <cuda_runtime.h>
#include <cuda_fp16.h>
#include <cstdint>

// ---------------------------------------------------------------------------
// GCN layer on GB300 (sm_103a). 3-kernel forked pipeline:
//   branch A (main): gemm (h = xW + b, FFMA2 row-pair, fp16 h)
//   branch B (side): scatter_direct — per-row fixed-capacity buckets,
//                    pos = atomicAdd(cursor), slots[row*64+pos] = (col,val)
//   join -> gather (half-warp edges, 8/iter, fused PReLU; resets cursors)
// Cursor doubles as row count; gather zeroes it for the next graph replay.
// ---------------------------------------------------------------------------

#define IN_FT   128
#define OUT_FT  64
#define N_CAP   100096
#define CAPB    64          // slots per row (avg degree 16; P(overflow)~0)

typedef unsigned long long u64;

static __device__ __half g_h[(size_t)N_CAP * OUT_FT];        // 12.8 MB
static __device__ int    g_cur[N_CAP];                       // zero at entry
static __device__ int2   g_slots[(size_t)N_CAP * CAPB];      // 51.2 MB

// ---- packed fp32x2 helpers -------------------------------------------------
__device__ __forceinline__ u64 pack2(float lo, float hi) {
    u64 r;
    asm("mov.b64 %0, {%1, %2};" : "=l"(r) : "f"(lo), "f"(hi));
    return r;
}
__device__ __forceinline__ float2 unpack2(u64 v) {
    float2 r;
    asm("mov.b64 {%0, %1}, %2;" : "=f"(r.x), "=f"(r.y) : "l"(v));
    return r;
}
__device__ __forceinline__ u64 fma2(u64 a, u64 b, u64 c) {
    u64 d;
    asm("fma.rn.f32x2 %0, %1, %2, %3;" : "=l"(d) : "l"(a), "l"(b), "l"(c));
    return d;
}

// ---------------------------------------------------------------------------
// A1: GEMM (64-row tile, 128 threads). Xs transposed: Xs[k*64 + row].
// Thread = 4 row-pairs (8 rows) x 4 cols, FFMA2 accumulators.
// ---------------------------------------------------------------------------
__global__ __launch_bounds__(128)
void gemm_kernel(const float* __restrict__ x,
                 const float* __restrict__ W,
                 const float* __restrict__ b,
                 int N) {
    __shared__ float Xs[IN_FT * 64];   // 32 KB, [k][row]

    const int tid  = threadIdx.x;
    const int row0 = blockIdx.x * 64;

    {
        const int r    = tid & 63;
        const int grow = row0 + r;
        const int c4b  = (tid >> 6) * 16;
        const bool ok  = (grow < N);
        const float4* xr = reinterpret_cast<const float4*>(x + (size_t)grow * IN_FT);
        #pragma unroll
        for (int p = 0; p < 16; p++) {
            const int c4 = c4b + p;
            float4 v = make_float4(0.f, 0.f, 0.f, 0.f);
            if (ok) v = xr[c4];
            Xs[(c4 * 4 + 0) * 64 + r] = v.x;
            Xs[(c4 * 4 + 1) * 64 + r] = v.y;
            Xs[(c4 * 4 + 2) * 64 + r] = v.z;
            Xs[(c4 * 4 + 3) * 64 + r] = v.w;
        }
    }
    __syncthreads();

    const int tx = tid & 15;   // cols [4*tx, 4*tx+4)
    const int ty = tid >> 4;   // rows [ty*8, ty*8+8) as 4 pairs

    u64 acc[4][4];
    #pragma unroll
    for (int i = 0; i < 4; i++)
        #pragma unroll
        for (int j = 0; j < 4; j++) acc[i][j] = 0ULL;

    const float4* __restrict__ Wg = reinterpret_cast<const float4*>(W);

    #pragma unroll 4
    for (int k = 0; k < IN_FT; k++) {
        const float4 w = __ldg(&Wg[k * 16 + tx]);
        u64 wd[4];
        wd[0] = pack2(w.x, w.x);
        wd[1] = pack2(w.y, w.y);
        wd[2] = pack2(w.z, w.z);
        wd[3] = pack2(w.w, w.w);

        const u64* xr = reinterpret_cast<const u64*>(&Xs[k * 64 + ty * 8]);
        u64 xp[4];
        xp[0] = xr[0]; xp[1] = xr[1]; xp[2] = xr[2]; xp[3] = xr[3];

        #pragma unroll
        for (int i = 0; i < 4; i++)
            #pragma unroll
            for (int j = 0; j < 4; j++)
                acc[i][j] = fma2(xp[i], wd[j], acc[i][j]);
    }

    const float4 bv = __ldg(reinterpret_cast<const float4*>(b) + tx);
    #pragma unroll
    for (int i = 0; i < 4; i++) {
        const float2 c0 = unpack2(acc[i][0]);
        const float2 c1 = unpack2(acc[i][1]);
        const float2 c2 = unpack2(acc[i][2]);
        const float2 c3 = unpack2(acc[i][3]);
        const int r0 = row0 + ty * 8 + 2 * i;
        if (r0 < N) {
            __half2 ha = __floats2half2_rn(c0.x + bv.x, c1.x + bv.y);
            __half2 hb = __floats2half2_rn(c2.x + bv.z, c3.x + bv.w);
            __half2* dst = reinterpret_cast<__half2*>(
                               g_h + (size_t)r0 * OUT_FT + tx * 4);
            dst[0] = ha; dst[1] = hb;
        }
        if (r0 + 1 < N) {
            __half2 ha = __floats2half2_rn(c0.y + bv.x, c1.y + bv.y);
            __half2 hb = __floats2half2_rn(c2.y + bv.z, c3.y + bv.w);
            __half2* dst = reinterpret_cast<__half2*>(
                               g_h + (size_t)(r0 + 1) * OUT_FT + tx * 4);
            dst[0] = ha; dst[1] = hb;
        }
    }
}

// ---------------------------------------------------------------------------
// B1: direct bucketed scatter. 4 edges per thread, vectorized loads.
// g_cur is zero at entry (gather resets it each call).
// ---------------------------------------------------------------------------
__global__ __launch_bounds__(256)
void scatter_kernel(const int*   __restrict__ erow,
                    const int*   __restrict__ ecol,
                    const float* __restrict__ eval,
                    int E) {
    const int idx = blockIdx.x * 256 + threadIdx.x;
    const int e   = idx * 4;
    if (e + 3 < E) {
        const int4   r = __ldg(reinterpret_cast<const int4*>(erow) + idx);
        const int4   c = __ldg(reinterpret_cast<const int4*>(ecol) + idx);
        const float4 v = __ldg(reinterpret_cast<const float4*>(eval) + idx);
        const int p0 = atomicAdd(&g_cur[r.x], 1);
        const int p1 = atomicAdd(&g_cur[r.y], 1);
        const int p2 = atomicAdd(&g_cur[r.z], 1);
        const int p3 = atomicAdd(&g_cur[r.w], 1);
        if (p0 < CAPB) g_slots[(size_t)r.x * CAPB + p0] = make_int2(c.x, __float_as_int(v.x));
        if (p1 < CAPB) g_slots[(size_t)r.y * CAPB + p1] = make_int2(c.y, __float_as_int(v.y));
        if (p2 < CAPB) g_slots[(size_t)r.z * CAPB + p2] = make_int2(c.z, __float_as_int(v.z));
        if (p3 < CAPB) g_slots[(size_t)r.w * CAPB + p3] = make_int2(c.w, __float_as_int(v.w));
    } else {
        for (int i = e; i < E; i++) {
            const int row = erow[i];
            const int p = atomicAdd(&g_cur[row], 1);
            if (p < CAPB)
                g_slots[(size_t)row * CAPB + p] =
                    make_int2(ecol[i], __float_as_int(eval[i]));
        }
    }
}

// ---------------------------------------------------------------------------
// J1: gather + fused PReLU. Warp = one row; half-warps own alternate edges
// (fp16 row = 128B = 16 lanes x uint2 = 4 cols/lane). Main loop: 8 edges per
// iteration, unpredicated. Resets the row cursor for the next call.
// ---------------------------------------------------------------------------
__global__ __launch_bounds__(256)
void gather_kernel(float* __restrict__ out,
                   const float* __restrict__ alpha,
                   int N) {
    const int lane = threadIdx.x & 31;
    const int sub  = lane & 15;    // col group: cols [sub*4, sub*4+4)
    const int half = lane >> 4;    // which edge of a pair
    const int row  = blockIdx.x * 8 + (threadIdx.x >> 5);
    if (row >= N) return;

    int cnt = g_cur[row];
    if (cnt > CAPB) cnt = CAPB;
    if (lane == 0) g_cur[row] = 0;       // restore invariant for next call

    const int2* __restrict__ seg = g_slots + (size_t)row * CAPB;

    float4 acc = make_float4(0.f, 0.f, 0.f, 0.f);
    const uint2* __restrict__ hh = reinterpret_cast<const uint2*>(g_h);

    int jb = 0;
    for (; jb + 7 < cnt; jb += 8) {
        const int2 p0 = __ldg(&seg[jb     + half]);
        const int2 p1 = __ldg(&seg[jb + 2 + half]);
        const int2 p2 = __ldg(&seg[jb + 4 + half]);
        const int2 p3 = __ldg(&seg[jb + 6 + half]);
        const uint2 q0 = __ldg(&hh[(size_t)p0.x * 16 + sub]);
        const uint2 q1 = __ldg(&hh[(size_t)p1.x * 16 + sub]);
        const uint2 q2 = __ldg(&hh[(size_t)p2.x * 16 + sub]);
        const uint2 q3 = __ldg(&hh[(size_t)p3.x * 16 + sub]);
        const float v0 = __int_as_float(p0.y);
        const float v1 = __int_as_float(p1.y);
        const float v2 = __int_as_float(p2.y);
        const float v3 = __int_as_float(p3.y);

        float2 a, b2;
        a  = __half22float2(*reinterpret_cast<const __half2*>(&q0.x));
        b2 = __half22float2(*reinterpret_cast<const __half2*>(&q0.y));
        acc.x = fmaf(v0, a.x, acc.x);  acc.y = fmaf(v0, a.y, acc.y);
        acc.z = fmaf(v0, b2.x, acc.z); acc.w = fmaf(v0, b2.y, acc.w);
        a  = __half22float2(*reinterpret_cast<const __half2*>(&q1.x));
        b2 = __half22float2(*reinterpret_cast<const __half2*>(&q1.y));
        acc.x = fmaf(v1, a.x, acc.x);  acc.y = fmaf(v1, a.y, acc.y);
        acc.z = fmaf(v1, b2.x, acc.z); acc.w = fmaf(v1, b2.y, acc.w);
        a  = __half22float2(*reinterpret_cast<const __half2*>(&q2.x));
        b2 = __half22float2(*reinterpret_cast<const __half2*>(&q2.y));
        acc.x = fmaf(v2, a.x, acc.x);  acc.y = fmaf(v2, a.y, acc.y);
        acc.z = fmaf(v2, b2.x, acc.z); acc.w = fmaf(v2, b2.y, acc.w);
        a  = __half22float2(*reinterpret_cast<const __half2*>(&q3.x));
        b2 = __half22float2(*reinterpret_cast<const __half2*>(&q3.y));
        acc.x = fmaf(v3, a.x, acc.x);  acc.y = fmaf(v3, a.y, acc.y);
        acc.z = fmaf(v3, b2.x, acc.z); acc.w = fmaf(v3, b2.y, acc.w);
    }
    for (; jb + half < cnt; jb += 2) {
        const int2 p = __ldg(&seg[jb + half]);
        const uint2 q = __ldg(&hh[(size_t)p.x * 16 + sub]);
        const float v = __int_as_float(p.y);
        const float2 a  = __half22float2(*reinterpret_cast<const __half2*>(&q.x));
        const float2 b2 = __half22float2(*reinterpret_cast<const __half2*>(&q.y));
        acc.x = fmaf(v, a.x, acc.x);  acc.y = fmaf(v, a.y, acc.y);
        acc.z = fmaf(v, b2.x, acc.z); acc.w = fmaf(v, b2.y, acc.w);
    }

    // combine the two half-warp partials (same cols, different edges)
    acc.x += __shfl_xor_sync(0xffffffffu, acc.x, 16);
    acc.y += __shfl_xor_sync(0xffffffffu, acc.y, 16);
    acc.z += __shfl_xor_sync(0xffffffffu, acc.z, 16);
    acc.w += __shfl_xor_sync(0xffffffffu, acc.w, 16);

    if (half == 0) {
        const float al = __ldg(alpha);
        acc.x = acc.x >= 0.f ? acc.x : al * acc.x;
        acc.y = acc.y >= 0.f ? acc.y : al * acc.y;
        acc.z = acc.z >= 0.f ? acc.z : al * acc.z;
        acc.w = acc.w >= 0.f ? acc.w : al * acc.w;
        reinterpret_cast<float4*>(out)[(size_t)row * 16 + sub] = acc;
    }
}

// ---------------------------------------------------------------------------
// Launch. Inputs: x, W, b, alpha, edge_row, edge_col, edge_val
// Fork-join: GEMM on the capture stream, bucketed scatter on a side stream.
// ---------------------------------------------------------------------------
extern "C" void kernel_launch(void* const* d_in, const int* in_sizes, int n_in,
                              void* d_out, int out_size) {
    const float* x     = (const float*)d_in[0];
    const float* W     = (const float*)d_in[1];
    const float* b     = (const float*)d_in[2];
    const float* alpha = (const float*)d_in[3];
    const int*   erow  = (const int*)  d_in[4];
    const int*   ecol  = (const int*)  d_in[5];
    const float* eval  = (const float*)d_in[6];

    const int N = in_sizes[0] / IN_FT;
    const int E = in_sizes[4];
    float* out = (float*)d_out;

    const int EB4 = (E + 1023) / 1024;   // 4 edges/thread, 256 thr/block

    static cudaStream_t s_side = nullptr;
    static cudaEvent_t  ev_fork = nullptr, ev_join = nullptr;
    if (s_side == nullptr) {
        cudaStreamCreateWithFlags(&s_side, cudaStreamNonBlocking);
        cudaEventCreateWithFlags(&ev_fork, cudaEventDisableTiming);
        cudaEventCreateWithFlags(&ev_join, cudaEventDisableTiming);
    }

    if (s_side != nullptr && ev_fork != nullptr && ev_join != nullptr) {
        cudaEventRecord(ev_fork, 0);
        cudaStreamWaitEvent(s_side, ev_fork, 0);
        // branch A
        gemm_kernel<<<(N + 63) / 64, 128>>>(x, W, b, N);
        // branch B
        scatter_kernel<<<EB4, 256, 0, s_side>>>(erow, ecol, eval, E);
        // join
        cudaEventRecord(ev_join, s_side);
        cudaStreamWaitEvent(0, ev_join, 0);
        gather_kernel<<<(N + 7) / 8, 256>>>(out, alpha, N);
    } else {
        gemm_kernel   <<<(N + 63) / 64, 128>>>(x, W, b, N);
        scatter_kernel<<<EB4, 256>>>(erow, ecol, eval, E);
        gather_kernel <<<(N + 7) / 8, 256>>>(out, alpha, N);
    }
}

// round 9
// speedup vs baseline: 1.6919x; 1.6919x over previous
#include <cuda_runtime.h>
#include <cuda_fp16.h>
#include <mma.h>
#include <cstdint>

using namespace nvcuda;

// ---------------------------------------------------------------------------
// GCN layer on GB300 (sm_103a). 5-kernel pipeline (serial-dominated):
//   gemm  : h = xW + b via wmma HMMA (fp16 inputs, fp32 accum, fp16 h out)
//   hist  : per-row counts; atomicAdd return = edge rank within row
//   scanB : block exclusive scan + arrival-order base claim -> {start,count}
//   scatter: permute edges into CSR pair array (no atomics)
//   gather: warp-per-row SpMM + fused PReLU (half-warp edges, 8/iter)
// ---------------------------------------------------------------------------

#define IN_FT   128
#define OUT_FT  64
#define N_CAP   131072
#define E_CAP   1605632

static __device__ __half         g_h[(size_t)N_CAP * OUT_FT];  // 12.8 MB
static __device__ int            g_cnt[N_CAP + 2];   // zero at entry
static __device__ int2           g_rowseg[N_CAP];    // {start, count} per row
static __device__ int            g_ebase;            // arrival-order allocator
static __device__ unsigned short g_rank[E_CAP];      // edge rank within row
static __device__ int2           g_pairs[E_CAP];     // CSR (col, val bits)

// ---------------------------------------------------------------------------
// K1: wmma GEMM. Block = 64 rows x 64 cols, K=128. 128 threads (4 warps).
// Xs [64][136] fp16 (pitch 272B), Ws [128][72] fp16 (pitch 144B).
// Accum staged to Os [64][68] fp32 overlapping dead Xs, then bias+fp16 store.
// ---------------------------------------------------------------------------
#define XS_PITCH 136
#define WS_PITCH 72
#define OS_PITCH 68
#define XS_BYTES (64 * XS_PITCH * 2)     // 17408
#define WS_BYTES (128 * WS_PITCH * 2)    // 18432

__global__ __launch_bounds__(128)
void gemm_kernel(const float* __restrict__ x,
                 const float* __restrict__ W,
                 const float* __restrict__ b,
                 int N) {
    __shared__ __align__(32) unsigned char smem[XS_BYTES + WS_BYTES];
    __half* Xs = reinterpret_cast<__half*>(smem);
    __half* Ws = reinterpret_cast<__half*>(smem + XS_BYTES);
    float*  Os = reinterpret_cast<float*>(smem);      // overlaps Xs (dead)

    const int tid  = threadIdx.x;
    const int row0 = blockIdx.x * 64;

    // Stage X tile (fp32 -> fp16). 2 threads per row, 16 float4 each.
    {
        const int r    = tid & 63;
        const int grow = row0 + r;
        const bool ok  = (grow < N);
        const float4* xr = reinterpret_cast<const float4*>(x + (size_t)grow * IN_FT);
        const int c4b = (tid >> 6) * 16;
        #pragma unroll
        for (int p = 0; p < 16; p++) {
            const int c4 = c4b + p;
            float4 v = make_float4(0.f, 0.f, 0.f, 0.f);
            if (ok) v = xr[c4];
            __half2 h0 = __floats2half2_rn(v.x, v.y);
            __half2 h1 = __floats2half2_rn(v.z, v.w);
            *reinterpret_cast<__half2*>(&Xs[r * XS_PITCH + c4 * 4])     = h0;
            *reinterpret_cast<__half2*>(&Xs[r * XS_PITCH + c4 * 4 + 2]) = h1;
        }
    }
    // Stage W tile (fp32 -> fp16). Thread = one K row (128 threads = 128 rows).
    {
        const int k = tid;
        const float4* wr = reinterpret_cast<const float4*>(W + (size_t)k * OUT_FT);
        #pragma unroll
        for (int p = 0; p < 16; p++) {
            const float4 v = __ldg(&wr[p]);
            __half2 h0 = __floats2half2_rn(v.x, v.y);
            __half2 h1 = __floats2half2_rn(v.z, v.w);
            *reinterpret_cast<__half2*>(&Ws[k * WS_PITCH + p * 4])     = h0;
            *reinterpret_cast<__half2*>(&Ws[k * WS_PITCH + p * 4 + 2]) = h1;
        }
    }
    __syncthreads();

    // Warp w owns rows [w*16, w*16+16) x all 64 cols (4 tiles).
    const int wid = tid >> 5;
    wmma::fragment<wmma::accumulator, 16, 16, 16, float> c[4];
    #pragma unroll
    for (int j = 0; j < 4; j++) wmma::fill_fragment(c[j], 0.0f);

    #pragma unroll
    for (int k = 0; k < 8; k++) {
        wmma::fragment<wmma::matrix_a, 16, 16, 16, __half, wmma::row_major> a;
        wmma::load_matrix_sync(a, &Xs[(wid * 16) * XS_PITCH + k * 16], XS_PITCH);
        #pragma unroll
        for (int j = 0; j < 4; j++) {
            wmma::fragment<wmma::matrix_b, 16, 16, 16, __half, wmma::row_major> bf;
            wmma::load_matrix_sync(bf, &Ws[(k * 16) * WS_PITCH + j * 16], WS_PITCH);
            wmma::mma_sync(c[j], a, bf, c[j]);
        }
    }

    __syncthreads();   // Xs fully consumed; Os may overwrite
    #pragma unroll
    for (int j = 0; j < 4; j++)
        wmma::store_matrix_sync(&Os[(wid * 16) * OS_PITCH + j * 16], c[j],
                                OS_PITCH, wmma::mem_row_major);
    __syncthreads();

    // Epilogue: bias add (fp32), convert fp16, store. 2 threads/row, 32 cols ea.
    {
        const int r    = tid & 63;
        const int grow = row0 + r;
        if (grow < N) {
            const int cb = (tid >> 6) * 32;
            #pragma unroll
            for (int p = 0; p < 8; p++) {
                const int cc = cb + p * 4;
                const float4 v  = *reinterpret_cast<const float4*>(&Os[r * OS_PITCH + cc]);
                const float4 bv = __ldg(reinterpret_cast<const float4*>(b) + (cc >> 2));
                __half2 h0 = __floats2half2_rn(v.x + bv.x, v.y + bv.y);
                __half2 h1 = __floats2half2_rn(v.z + bv.z, v.w + bv.w);
                __half2* dst = reinterpret_cast<__half2*>(g_h + (size_t)grow * OUT_FT + cc);
                dst[0] = h0; dst[1] = h1;
            }
        }
    }
}

// ---------------------------------------------------------------------------
// K2: histogram with rank. 4 edges per thread. Resets g_ebase.
// ---------------------------------------------------------------------------
__global__ __launch_bounds__(256)
void hist_kernel(const int* __restrict__ erow, int E) {
    if (blockIdx.x == 0 && threadIdx.x == 0) g_ebase = 0;
    const int idx = blockIdx.x * 256 + threadIdx.x;
    const int e   = idx * 4;
    if (e + 3 < E) {
        const int4 r = __ldg(reinterpret_cast<const int4*>(erow) + idx);
        const int k0 = atomicAdd(&g_cnt[r.x], 1);
        const int k1 = atomicAdd(&g_cnt[r.y], 1);
        const int k2 = atomicAdd(&g_cnt[r.z], 1);
        const int k3 = atomicAdd(&g_cnt[r.w], 1);
        ushort4 rk;
        rk.x = (unsigned short)k0; rk.y = (unsigned short)k1;
        rk.z = (unsigned short)k2; rk.w = (unsigned short)k3;
        *reinterpret_cast<ushort4*>(g_rank + e) = rk;
    } else {
        for (int i = e; i < E; i++)
            g_rank[i] = (unsigned short)atomicAdd(&g_cnt[erow[i]], 1);
    }
}

// ---------------------------------------------------------------------------
// K3: block scan + arrival-order base claim -> per-row {start,count}.
// Resets g_cnt (zero-at-entry invariant for graph replays).
// ---------------------------------------------------------------------------
__global__ __launch_bounds__(256)
void scanB_kernel(int N) {
    __shared__ int ws[8];
    __shared__ int sbase;
    const int tid  = threadIdx.x;
    const int lane = tid & 31;
    const int wid  = tid >> 5;
    const int idx  = blockIdx.x * 256 + tid;

    const int v = (idx < N) ? g_cnt[idx] : 0;
    int inc = v;
    #pragma unroll
    for (int off = 1; off < 32; off <<= 1) {
        const int t = __shfl_up_sync(0xffffffffu, inc, off);
        if (lane >= off) inc += t;
    }
    if (lane == 31) ws[wid] = inc;
    __syncthreads();
    if (wid == 0) {
        int wv = (lane < 8) ? ws[lane] : 0;
        #pragma unroll
        for (int off = 1; off < 8; off <<= 1) {
            const int t = __shfl_up_sync(0xffffffffu, wv, off);
            if (lane >= off) wv += t;
        }
        if (lane < 8) ws[lane] = wv;
        if (lane == 7) sbase = atomicAdd(&g_ebase, wv);   // claim range
    }
    __syncthreads();
    if (idx < N) {
        const int wofs = (wid > 0) ? ws[wid - 1] : 0;
        g_rowseg[idx] = make_int2(sbase + wofs + inc - v, v);
        g_cnt[idx] = 0;
    }
}

// ---------------------------------------------------------------------------
// K4: scatter into CSR (no atomics). 4 edges per thread.
// ---------------------------------------------------------------------------
__global__ __launch_bounds__(256)
void scatter_kernel(const int*   __restrict__ erow,
                    const int*   __restrict__ ecol,
                    const float* __restrict__ eval,
                    int E) {
    const int idx = blockIdx.x * 256 + threadIdx.x;
    const int e   = idx * 4;
    if (e + 3 < E) {
        const int4    r  = __ldg(reinterpret_cast<const int4*>(erow) + idx);
        const int4    c  = __ldg(reinterpret_cast<const int4*>(ecol) + idx);
        const float4  v  = __ldg(reinterpret_cast<const float4*>(eval) + idx);
        const ushort4 rk = *reinterpret_cast<const ushort4*>(g_rank + e);
        const int p0 = g_rowseg[r.x].x + (int)rk.x;
        const int p1 = g_rowseg[r.y].x + (int)rk.y;
        const int p2 = g_rowseg[r.z].x + (int)rk.z;
        const int p3 = g_rowseg[r.w].x + (int)rk.w;
        g_pairs[p0] = make_int2(c.x, __float_as_int(v.x));
        g_pairs[p1] = make_int2(c.y, __float_as_int(v.y));
        g_pairs[p2] = make_int2(c.z, __float_as_int(v.z));
        g_pairs[p3] = make_int2(c.w, __float_as_int(v.w));
    } else {
        for (int i = e; i < E; i++) {
            const int row = erow[i];
            const int pos = g_rowseg[row].x + (int)g_rank[i];
            g_pairs[pos] = make_int2(ecol[i], __float_as_int(eval[i]));
        }
    }
}

// ---------------------------------------------------------------------------
// K5: gather + fused PReLU. Warp = one row; half-warps own alternate edges
// (fp16 row = 128B = 16 lanes x uint2). Main loop: 8 edges/iter unpredicated.
// ---------------------------------------------------------------------------
__global__ __launch_bounds__(256)
void gather_kernel(float* __restrict__ out,
                   const float* __restrict__ alpha,
                   int N) {
    const int lane = threadIdx.x & 31;
    const int sub  = lane & 15;    // col group: cols [sub*4, sub*4+4)
    const int half = lane >> 4;    // which edge of a pair
    const int row  = blockIdx.x * 8 + (threadIdx.x >> 5);
    if (row >= N) return;

    const int2 seg  = g_rowseg[row];
    const int  endj = seg.x + seg.y;

    float4 acc = make_float4(0.f, 0.f, 0.f, 0.f);
    const uint2* __restrict__ hh = reinterpret_cast<const uint2*>(g_h);

    int jb = seg.x;
    for (; jb + 7 < endj; jb += 8) {
        const int2 p0 = __ldg(&g_pairs[jb     + half]);
        const int2 p1 = __ldg(&g_pairs[jb + 2 + half]);
        const int2 p2 = __ldg(&g_pairs[jb + 4 + half]);
        const int2 p3 = __ldg(&g_pairs[jb + 6 + half]);
        const uint2 q0 = __ldg(&hh[(size_t)p0.x * 16 + sub]);
        const uint2 q1 = __ldg(&hh[(size_t)p1.x * 16 + sub]);
        const uint2 q2 = __ldg(&hh[(size_t)p2.x * 16 + sub]);
        const uint2 q3 = __ldg(&hh[(size_t)p3.x * 16 + sub]);
        const float v0 = __int_as_float(p0.y);
        const float v1 = __int_as_float(p1.y);
        const float v2 = __int_as_float(p2.y);
        const float v3 = __int_as_float(p3.y);

        float2 a, b2;
        a  = __half22float2(*reinterpret_cast<const __half2*>(&q0.x));
        b2 = __half22float2(*reinterpret_cast<const __half2*>(&q0.y));
        acc.x = fmaf(v0, a.x, acc.x);  acc.y = fmaf(v0, a.y, acc.y);
        acc.z = fmaf(v0, b2.x, acc.z); acc.w = fmaf(v0, b2.y, acc.w);
        a  = __half22float2(*reinterpret_cast<const __half2*>(&q1.x));
        b2 = __half22float2(*reinterpret_cast<const __half2*>(&q1.y));
        acc.x = fmaf(v1, a.x, acc.x);  acc.y = fmaf(v1, a.y, acc.y);
        acc.z = fmaf(v1, b2.x, acc.z); acc.w = fmaf(v1, b2.y, acc.w);
        a  = __half22float2(*reinterpret_cast<const __half2*>(&q2.x));
        b2 = __half22float2(*reinterpret_cast<const __half2*>(&q2.y));
        acc.x = fmaf(v2, a.x, acc.x);  acc.y = fmaf(v2, a.y, acc.y);
        acc.z = fmaf(v2, b2.x, acc.z); acc.w = fmaf(v2, b2.y, acc.w);
        a  = __half22float2(*reinterpret_cast<const __half2*>(&q3.x));
        b2 = __half22float2(*reinterpret_cast<const __half2*>(&q3.y));
        acc.x = fmaf(v3, a.x, acc.x);  acc.y = fmaf(v3, a.y, acc.y);
        acc.z = fmaf(v3, b2.x, acc.z); acc.w = fmaf(v3, b2.y, acc.w);
    }
    for (; jb + half < endj; jb += 2) {
        const int2 p = __ldg(&g_pairs[jb + half]);
        const uint2 q = __ldg(&hh[(size_t)p.x * 16 + sub]);
        const float v = __int_as_float(p.y);
        const float2 a  = __half22float2(*reinterpret_cast<const __half2*>(&q.x));
        const float2 b2 = __half22float2(*reinterpret_cast<const __half2*>(&q.y));
        acc.x = fmaf(v, a.x, acc.x);  acc.y = fmaf(v, a.y, acc.y);
        acc.z = fmaf(v, b2.x, acc.z); acc.w = fmaf(v, b2.y, acc.w);
    }

    acc.x += __shfl_xor_sync(0xffffffffu, acc.x, 16);
    acc.y += __shfl_xor_sync(0xffffffffu, acc.y, 16);
    acc.z += __shfl_xor_sync(0xffffffffu, acc.z, 16);
    acc.w += __shfl_xor_sync(0xffffffffu, acc.w, 16);

    if (half == 0) {
        const float al = __ldg(alpha);
        acc.x = acc.x >= 0.f ? acc.x : al * acc.x;
        acc.y = acc.y >= 0.f ? acc.y : al * acc.y;
        acc.z = acc.z >= 0.f ? acc.z : al * acc.z;
        acc.w = acc.w >= 0.f ? acc.w : al * acc.w;
        reinterpret_cast<float4*>(out)[(size_t)row * 16 + sub] = acc;
    }
}

// ---------------------------------------------------------------------------
// Launch. Inputs: x, W, b, alpha, edge_row, edge_col, edge_val
// Fork kept (free); machine is grid-serial in practice.
// ---------------------------------------------------------------------------
extern "C" void kernel_launch(void* const* d_in, const int* in_sizes, int n_in,
                              void* d_out, int out_size) {
    const float* x     = (const float*)d_in[0];
    const float* W     = (const float*)d_in[1];
    const float* b     = (const float*)d_in[2];
    const float* alpha = (const float*)d_in[3];
    const int*   erow  = (const int*)  d_in[4];
    const int*   ecol  = (const int*)  d_in[5];
    const float* eval  = (const float*)d_in[6];

    const int N  = in_sizes[0] / IN_FT;
    const int E  = in_sizes[4];
    const int NB = (N + 255) / 256;
    float* out = (float*)d_out;

    const int EB4 = (E + 1023) / 1024;   // 4 edges/thread

    static cudaStream_t s_side = nullptr;
    static cudaEvent_t  ev_fork = nullptr, ev_join = nullptr;
    if (s_side == nullptr) {
        cudaStreamCreateWithFlags(&s_side, cudaStreamNonBlocking);
        cudaEventCreateWithFlags(&ev_fork, cudaEventDisableTiming);
        cudaEventCreateWithFlags(&ev_join, cudaEventDisableTiming);
    }

    if (s_side != nullptr && ev_fork != nullptr && ev_join != nullptr) {
        cudaEventRecord(ev_fork, 0);
        cudaStreamWaitEvent(s_side, ev_fork, 0);
        // branch A: tensor-core GEMM
        gemm_kernel<<<(N + 63) / 64, 128>>>(x, W, b, N);
        // branch B: CSR build
        hist_kernel   <<<EB4, 256, 0, s_side>>>(erow, E);
        scanB_kernel  <<<NB, 256, 0, s_side>>>(N);
        scatter_kernel<<<EB4, 256, 0, s_side>>>(erow, ecol, eval, E);
        // join
        cudaEventRecord(ev_join, s_side);
        cudaStreamWaitEvent(0, ev_join, 0);
        gather_kernel<<<(N + 7) / 8, 256>>>(out, alpha, N);
    } else {
        gemm_kernel   <<<(N + 63) / 64, 128>>>(x, W, b, N);
        hist_kernel   <<<EB4, 256>>>(erow, E);
        scanB_kernel  <<<NB, 256>>>(N);
        scatter_kernel<<<EB4, 256>>>(erow, ecol, eval, E);
        gather_kernel <<<(N + 7) / 8, 256>>>(out, alpha, N);
    }
}

// round 10
// speedup vs baseline: 1.7168x; 1.0147x over previous
#include <cuda_runtime.h>
#include <cuda_fp16.h>
#include <mma.h>
#include <cstdint>

using namespace nvcuda;

// ---------------------------------------------------------------------------
// GCN layer on GB300 (sm_103a). Serial 4-kernel pipeline:
//   K1 gemm+hist : h = xW + b via wmma HMMA (fp16 in, fp32 acc, fp16 h out)
//                  + fused edge histogram; atomicAdd return = rank in row
//                  (hist hides behind the tensor-pipe work)
//   K2 scanB     : block exclusive scan + arrival-order base claim
//   K3 scatter   : permute edges into CSR pair array (no atomics)
//   K4 gather    : warp-per-row SpMM + fused PReLU (half-warp, 8 edges/iter)
// ---------------------------------------------------------------------------

#define IN_FT   128
#define OUT_FT  64
#define N_CAP   131072
#define E_CAP   1605632

static __device__ __half         g_h[(size_t)N_CAP * OUT_FT];  // 12.8 MB
static __device__ int            g_cnt[N_CAP + 2];   // zero at entry
static __device__ int2           g_rowseg[N_CAP];    // {start, count} per row
static __device__ int            g_ebase;            // arrival-order allocator
static __device__ unsigned short g_rank[E_CAP];      // edge rank within row
static __device__ int2           g_pairs[E_CAP];     // CSR (col, val bits)

// ---------------------------------------------------------------------------
// K1: wmma GEMM + fused histogram. Block = 64 rows x 64 cols, K=128,
// 128 threads (4 warps). Xs [64][136] fp16, Ws [128][72] fp16.
// Accum staged to Os fp32 (overlaps dead Xs), bias+fp16 epilogue.
// Hist tail: grid-strided, 4 edges/thread vectorized.
// ---------------------------------------------------------------------------
#define XS_PITCH 136
#define WS_PITCH 72
#define OS_PITCH 68
#define XS_BYTES (64 * XS_PITCH * 2)     // 17408
#define WS_BYTES (128 * WS_PITCH * 2)    // 18432

__global__ __launch_bounds__(128)
void gemm_hist_kernel(const float* __restrict__ x,
                      const float* __restrict__ W,
                      const float* __restrict__ b,
                      const int*   __restrict__ erow,
                      int N, int E) {
    __shared__ __align__(32) unsigned char smem[XS_BYTES + WS_BYTES];
    __half* Xs = reinterpret_cast<__half*>(smem);
    __half* Ws = reinterpret_cast<__half*>(smem + XS_BYTES);
    float*  Os = reinterpret_cast<float*>(smem);      // overlaps Xs (dead)

    const int tid  = threadIdx.x;
    const int row0 = blockIdx.x * 64;

    if (blockIdx.x == 0 && tid == 0) g_ebase = 0;

    // Stage X tile (fp32 -> fp16). 2 threads per row, 16 float4 per thread.
    {
        const int r    = tid & 63;
        const int grow = row0 + r;
        const bool ok  = (grow < N);
        const float4* xr = reinterpret_cast<const float4*>(x + (size_t)grow * IN_FT);
        const int c4b = (tid >> 6) * 16;
        #pragma unroll
        for (int p = 0; p < 16; p++) {
            const int c4 = c4b + p;
            float4 v = make_float4(0.f, 0.f, 0.f, 0.f);
            if (ok) v = xr[c4];
            __half2 h0 = __floats2half2_rn(v.x, v.y);
            __half2 h1 = __floats2half2_rn(v.z, v.w);
            *reinterpret_cast<__half2*>(&Xs[r * XS_PITCH + c4 * 4])     = h0;
            *reinterpret_cast<__half2*>(&Xs[r * XS_PITCH + c4 * 4 + 2]) = h1;
        }
    }
    // Stage W tile (fp32 -> fp16). Thread = one K row.
    {
        const int k = tid;
        const float4* wr = reinterpret_cast<const float4*>(W + (size_t)k * OUT_FT);
        #pragma unroll
        for (int p = 0; p < 16; p++) {
            const float4 v = __ldg(&wr[p]);
            __half2 h0 = __floats2half2_rn(v.x, v.y);
            __half2 h1 = __floats2half2_rn(v.z, v.w);
            *reinterpret_cast<__half2*>(&Ws[k * WS_PITCH + p * 4])     = h0;
            *reinterpret_cast<__half2*>(&Ws[k * WS_PITCH + p * 4 + 2]) = h1;
        }
    }
    __syncthreads();

    // Warp w owns rows [w*16, w*16+16) x all 64 cols (4 n-tiles).
    const int wid = tid >> 5;
    wmma::fragment<wmma::accumulator, 16, 16, 16, float> c[4];
    #pragma unroll
    for (int j = 0; j < 4; j++) wmma::fill_fragment(c[j], 0.0f);

    #pragma unroll
    for (int k = 0; k < 8; k++) {
        wmma::fragment<wmma::matrix_a, 16, 16, 16, __half, wmma::row_major> a;
        wmma::load_matrix_sync(a, &Xs[(wid * 16) * XS_PITCH + k * 16], XS_PITCH);
        #pragma unroll
        for (int j = 0; j < 4; j++) {
            wmma::fragment<wmma::matrix_b, 16, 16, 16, __half, wmma::row_major> bf;
            wmma::load_matrix_sync(bf, &Ws[(k * 16) * WS_PITCH + j * 16], WS_PITCH);
            wmma::mma_sync(c[j], a, bf, c[j]);
        }
    }

    __syncthreads();   // Xs fully consumed; Os may overwrite
    #pragma unroll
    for (int j = 0; j < 4; j++)
        wmma::store_matrix_sync(&Os[(wid * 16) * OS_PITCH + j * 16], c[j],
                                OS_PITCH, wmma::mem_row_major);
    __syncthreads();

    // Epilogue: bias add (fp32), fp16 convert, store.
    {
        const int r    = tid & 63;
        const int grow = row0 + r;
        if (grow < N) {
            const int cb = (tid >> 6) * 32;
            #pragma unroll
            for (int p = 0; p < 8; p++) {
                const int cc = cb + p * 4;
                const float4 v  = *reinterpret_cast<const float4*>(&Os[r * OS_PITCH + cc]);
                const float4 bv = __ldg(reinterpret_cast<const float4*>(b) + (cc >> 2));
                __half2 h0 = __floats2half2_rn(v.x + bv.x, v.y + bv.y);
                __half2 h1 = __floats2half2_rn(v.z + bv.z, v.w + bv.w);
                __half2* dst = reinterpret_cast<__half2*>(g_h + (size_t)grow * OUT_FT + cc);
                dst[0] = h0; dst[1] = h1;
            }
        }
    }

    // Fused histogram tail: grid-strided, 4 edges per step per thread.
    {
        const int nthreads = gridDim.x * 128;
        const int gtid     = blockIdx.x * 128 + tid;
        const int nquad    = E >> 2;                   // full int4 quads
        for (int i = gtid; i < nquad; i += nthreads) {
            const int4 r = __ldg(reinterpret_cast<const int4*>(erow) + i);
            const int k0 = atomicAdd(&g_cnt[r.x], 1);
            const int k1 = atomicAdd(&g_cnt[r.y], 1);
            const int k2 = atomicAdd(&g_cnt[r.z], 1);
            const int k3 = atomicAdd(&g_cnt[r.w], 1);
            ushort4 rk;
            rk.x = (unsigned short)k0; rk.y = (unsigned short)k1;
            rk.z = (unsigned short)k2; rk.w = (unsigned short)k3;
            *reinterpret_cast<ushort4*>(g_rank + i * 4) = rk;
        }
        // tail edges
        if (gtid == 0) {
            for (int i = nquad * 4; i < E; i++)
                g_rank[i] = (unsigned short)atomicAdd(&g_cnt[erow[i]], 1);
        }
    }
}

// ---------------------------------------------------------------------------
// K2: block scan + arrival-order base claim -> per-row {start,count}.
// Resets g_cnt (zero-at-entry invariant across graph replays).
// ---------------------------------------------------------------------------
__global__ __launch_bounds__(256)
void scanB_kernel(int N) {
    __shared__ int ws[8];
    __shared__ int sbase;
    const int tid  = threadIdx.x;
    const int lane = tid & 31;
    const int wid  = tid >> 5;
    const int idx  = blockIdx.x * 256 + tid;

    const int v = (idx < N) ? g_cnt[idx] : 0;
    int inc = v;
    #pragma unroll
    for (int off = 1; off < 32; off <<= 1) {
        const int t = __shfl_up_sync(0xffffffffu, inc, off);
        if (lane >= off) inc += t;
    }
    if (lane == 31) ws[wid] = inc;
    __syncthreads();
    if (wid == 0) {
        int wv = (lane < 8) ? ws[lane] : 0;
        #pragma unroll
        for (int off = 1; off < 8; off <<= 1) {
            const int t = __shfl_up_sync(0xffffffffu, wv, off);
            if (lane >= off) wv += t;
        }
        if (lane < 8) ws[lane] = wv;
        if (lane == 7) sbase = atomicAdd(&g_ebase, wv);   // claim range
    }
    __syncthreads();
    if (idx < N) {
        const int wofs = (wid > 0) ? ws[wid - 1] : 0;
        g_rowseg[idx] = make_int2(sbase + wofs + inc - v, v);
        g_cnt[idx] = 0;
    }
}

// ---------------------------------------------------------------------------
// K3: scatter into CSR (no atomics). 4 edges per thread.
// ---------------------------------------------------------------------------
__global__ __launch_bounds__(256)
void scatter_kernel(const int*   __restrict__ erow,
                    const int*   __restrict__ ecol,
                    const float* __restrict__ eval,
                    int E) {
    const int idx = blockIdx.x * 256 + threadIdx.x;
    const int e   = idx * 4;
    if (e + 3 < E) {
        const int4    r  = __ldg(reinterpret_cast<const int4*>(erow) + idx);
        const int4    c  = __ldg(reinterpret_cast<const int4*>(ecol) + idx);
        const float4  v  = __ldg(reinterpret_cast<const float4*>(eval) + idx);
        const ushort4 rk = *reinterpret_cast<const ushort4*>(g_rank + e);
        const int p0 = g_rowseg[r.x].x + (int)rk.x;
        const int p1 = g_rowseg[r.y].x + (int)rk.y;
        const int p2 = g_rowseg[r.z].x + (int)rk.z;
        const int p3 = g_rowseg[r.w].x + (int)rk.w;
        g_pairs[p0] = make_int2(c.x, __float_as_int(v.x));
        g_pairs[p1] = make_int2(c.y, __float_as_int(v.y));
        g_pairs[p2] = make_int2(c.z, __float_as_int(v.z));
        g_pairs[p3] = make_int2(c.w, __float_as_int(v.w));
    } else {
        for (int i = e; i < E; i++) {
            const int row = erow[i];
            const int pos = g_rowseg[row].x + (int)g_rank[i];
            g_pairs[pos] = make_int2(ecol[i], __float_as_int(eval[i]));
        }
    }
}

// ---------------------------------------------------------------------------
// K4: gather + fused PReLU. Warp = one row; half-warps own alternate edges
// (fp16 row = 128B = 16 lanes x uint2). Main loop: 8 edges/iter unpredicated.
// ---------------------------------------------------------------------------
__global__ __launch_bounds__(256)
void gather_kernel(float* __restrict__ out,
                   const float* __restrict__ alpha,
                   int N) {
    const int lane = threadIdx.x & 31;
    const int sub  = lane & 15;    // col group: cols [sub*4, sub*4+4)
    const int half = lane >> 4;    // which edge of a pair
    const int row  = blockIdx.x * 8 + (threadIdx.x >> 5);
    if (row >= N) return;

    const int2 seg  = g_rowseg[row];
    const int  endj = seg.x + seg.y;

    float4 acc = make_float4(0.f, 0.f, 0.f, 0.f);
    const uint2* __restrict__ hh = reinterpret_cast<const uint2*>(g_h);

    int jb = seg.x;
    for (; jb + 7 < endj; jb += 8) {
        const int2 p0 = __ldg(&g_pairs[jb     + half]);
        const int2 p1 = __ldg(&g_pairs[jb + 2 + half]);
        const int2 p2 = __ldg(&g_pairs[jb + 4 + half]);
        const int2 p3 = __ldg(&g_pairs[jb + 6 + half]);
        const uint2 q0 = __ldg(&hh[(size_t)p0.x * 16 + sub]);
        const uint2 q1 = __ldg(&hh[(size_t)p1.x * 16 + sub]);
        const uint2 q2 = __ldg(&hh[(size_t)p2.x * 16 + sub]);
        const uint2 q3 = __ldg(&hh[(size_t)p3.x * 16 + sub]);
        const float v0 = __int_as_float(p0.y);
        const float v1 = __int_as_float(p1.y);
        const float v2 = __int_as_float(p2.y);
        const float v3 = __int_as_float(p3.y);

        float2 a, b2;
        a  = __half22float2(*reinterpret_cast<const __half2*>(&q0.x));
        b2 = __half22float2(*reinterpret_cast<const __half2*>(&q0.y));
        acc.x = fmaf(v0, a.x, acc.x);  acc.y = fmaf(v0, a.y, acc.y);
        acc.z = fmaf(v0, b2.x, acc.z); acc.w = fmaf(v0, b2.y, acc.w);
        a  = __half22float2(*reinterpret_cast<const __half2*>(&q1.x));
        b2 = __half22float2(*reinterpret_cast<const __half2*>(&q1.y));
        acc.x = fmaf(v1, a.x, acc.x);  acc.y = fmaf(v1, a.y, acc.y);
        acc.z = fmaf(v1, b2.x, acc.z); acc.w = fmaf(v1, b2.y, acc.w);
        a  = __half22float2(*reinterpret_cast<const __half2*>(&q2.x));
        b2 = __half22float2(*reinterpret_cast<const __half2*>(&q2.y));
        acc.x = fmaf(v2, a.x, acc.x);  acc.y = fmaf(v2, a.y, acc.y);
        acc.z = fmaf(v2, b2.x, acc.z); acc.w = fmaf(v2, b2.y, acc.w);
        a  = __half22float2(*reinterpret_cast<const __half2*>(&q3.x));
        b2 = __half22float2(*reinterpret_cast<const __half2*>(&q3.y));
        acc.x = fmaf(v3, a.x, acc.x);  acc.y = fmaf(v3, a.y, acc.y);
        acc.z = fmaf(v3, b2.x, acc.z); acc.w = fmaf(v3, b2.y, acc.w);
    }
    for (; jb + half < endj; jb += 2) {
        const int2 p = __ldg(&g_pairs[jb + half]);
        const uint2 q = __ldg(&hh[(size_t)p.x * 16 + sub]);
        const float v = __int_as_float(p.y);
        const float2 a  = __half22float2(*reinterpret_cast<const __half2*>(&q.x));
        const float2 b2 = __half22float2(*reinterpret_cast<const __half2*>(&q.y));
        acc.x = fmaf(v, a.x, acc.x);  acc.y = fmaf(v, a.y, acc.y);
        acc.z = fmaf(v, b2.x, acc.z); acc.w = fmaf(v, b2.y, acc.w);
    }

    acc.x += __shfl_xor_sync(0xffffffffu, acc.x, 16);
    acc.y += __shfl_xor_sync(0xffffffffu, acc.y, 16);
    acc.z += __shfl_xor_sync(0xffffffffu, acc.z, 16);
    acc.w += __shfl_xor_sync(0xffffffffu, acc.w, 16);

    if (half == 0) {
        const float al = __ldg(alpha);
        acc.x = acc.x >= 0.f ? acc.x : al * acc.x;
        acc.y = acc.y >= 0.f ? acc.y : al * acc.y;
        acc.z = acc.z >= 0.f ? acc.z : al * acc.z;
        acc.w = acc.w >= 0.f ? acc.w : al * acc.w;
        reinterpret_cast<float4*>(out)[(size_t)row * 16 + sub] = acc;
    }
}

// ---------------------------------------------------------------------------
// Launch. Inputs: x, W, b, alpha, edge_row, edge_col, edge_val
// Serial single-stream 4-kernel chain (hist hides inside the gemm).
// ---------------------------------------------------------------------------
extern "C" void kernel_launch(void* const* d_in, const int* in_sizes, int n_in,
                              void* d_out, int out_size) {
    const float* x     = (const float*)d_in[0];
    const float* W     = (const float*)d_in[1];
    const float* b     = (const float*)d_in[2];
    const float* alpha = (const float*)d_in[3];
    const int*   erow  = (const int*)  d_in[4];
    const int*   ecol  = (const int*)  d_in[5];
    const float* eval  = (const float*)d_in[6];

    const int N  = in_sizes[0] / IN_FT;
    const int E  = in_sizes[4];
    const int NB = (N + 255) / 256;
    float* out = (float*)d_out;

    const int EB4 = (E + 1023) / 1024;   // 4 edges/thread, 256 thr/block

    gemm_hist_kernel<<<(N + 63) / 64, 128>>>(x, W, b, erow, N, E);
    scanB_kernel    <<<NB, 256>>>(N);
    scatter_kernel  <<<EB4, 256>>>(erow, ecol, eval, E);
    gather_kernel   <<<(N + 7) / 8, 256>>>(out, alpha, N);
}